// round 13
// baseline (speedup 1.0000x reference)
#include <cuda_runtime.h>
#include <cuda_bf16.h>

// MLLoss: per-sample hinge loss over [B,16] f32 distances -> scalar mean.
// Labels int32.
//
// R13 = R12 (floor candidate: 48.29us kernel, 6335 GB/s) with the last
// untried micro-lever: 256-bit global loads (sm_100+). 2x LDG.256 per row
// instead of 4x LDG.128 -> half the load instructions, half the L1tex
// dispatch events, 64B-per-line coverage per instruction instead of 32B.

#define THREADS 256
#define BLOCKS  1216   // 8 blocks/SM x 152 SMs = one full wave

__device__ float        g_partial;   // zero at load; reset by last block each call
__device__ unsigned int g_count;

struct float8 { float v[8]; };

__device__ __forceinline__ float8 ldcs_v8(const float* p) {
    float8 r;
    asm("ld.global.cs.L2::256B.v8.f32 {%0,%1,%2,%3,%4,%5,%6,%7}, [%8];"
        : "=f"(r.v[0]), "=f"(r.v[1]), "=f"(r.v[2]), "=f"(r.v[3]),
          "=f"(r.v[4]), "=f"(r.v[5]), "=f"(r.v[6]), "=f"(r.v[7])
        : "l"(p));
    return r;
}

__global__ __launch_bounds__(THREADS, 8)
void mlloss_kernel(const float* __restrict__ dist,    // [B,16] f32
                   const int* __restrict__ doctor,    // [B] int32 {0,1,2}
                   const int* __restrict__ real_l,    // [B] int32 {0,1}
                   float* __restrict__ out,
                   int B, float inv_B)
{
    const int tid    = blockIdx.x * blockDim.x + threadIdx.x;
    const int stride = gridDim.x * blockDim.x;

    float acc = 0.0f;

    for (int row = tid; row < B; row += stride) {
        const int dl = __ldcs(&doctor[row]);
        const int rl = __ldcs(&real_l[row]);

        const float* rp = dist + (size_t)row * 16;
        const float8 lo = ldcs_v8(rp);       // cols 0..7
        const float8 hi = ldcs_v8(rp + 8);   // cols 8..15

        const float h0 = fmaxf(1.0f - lo.v[0], 0.0f);
        const float h1 = fmaxf(1.0f - lo.v[1], 0.0f);

        float hs = h0 + h1;
        #pragma unroll
        for (int i = 2; i < 8; i++) hs += fmaxf(1.0f - lo.v[i], 0.0f);
        #pragma unroll
        for (int i = 0; i < 8; i++) hs += fmaxf(1.0f - hi.v[i], 0.0f);

        const float loss = (dl == 0) ? (lo.v[0] + hs - h0)
                         : (dl == 1) ? (lo.v[1] + hs - h1)
                                     : ((rl == 0) ? h1 : h0);
        acc += loss;
    }

    // warp reduce
    #pragma unroll
    for (int off = 16; off > 0; off >>= 1)
        acc += __shfl_xor_sync(0xFFFFFFFFu, acc, off);

    __shared__ float warp_sums[THREADS / 32];
    const int lane = threadIdx.x & 31;
    const int wid  = threadIdx.x >> 5;
    if (lane == 0) warp_sums[wid] = acc;
    __syncthreads();

    if (wid == 0) {
        float v = (lane < THREADS / 32) ? warp_sums[lane] : 0.0f;
        #pragma unroll
        for (int off = 16; off > 0; off >>= 1)
            v += __shfl_xor_sync(0xFFFFFFFFu, v, off);

        if (lane == 0) {
            atomicAdd(&g_partial, v);
            __threadfence();
            const unsigned int ticket = atomicAdd(&g_count, 1u);
            if (ticket == gridDim.x - 1) {
                const float total = atomicAdd(&g_partial, 0.0f); // fenced read
                out[0] = total * inv_B;
                g_partial = 0.0f;
                g_count   = 0u;
                __threadfence();
            }
        }
    }
}

extern "C" void kernel_launch(void* const* d_in, const int* in_sizes, int n_in,
                              void* d_out, int out_size)
{
    const float* dist   = (const float*)d_in[0];
    const int*   doctor = (const int*)d_in[1];
    const int*   real_l = (const int*)d_in[2];
    float*       out    = (float*)d_out;

    const int B = in_sizes[1];
    const float inv_B = 1.0f / (float)B;

    mlloss_kernel<<<BLOCKS, THREADS>>>(dist, doctor, real_l, out, B, inv_B);
}

// round 14
// speedup vs baseline: 1.0058x; 1.0058x over previous
#include <cuda_runtime.h>
#include <cuda_bf16.h>

// MLLoss: per-sample hinge loss over [B,16] f32 distances -> scalar mean.
// Labels int32.
//
// FINAL = measured-fastest kernel (48.16-48.29us, 6335-6341 GB/s, DRAM 80%).
// Exhaustive evidence (R2-R13): strided/coalesced/predicated LDG.128,
// LDG.256, and TMA bulk all cap at <=6.34 TB/s (path-independent ceiling);
// traffic is irreducible (305 MB, 64B DRAM granularity defeats skipping);
// work stealing/shuffle schemes cost more than they save. 305MB/6.34TB/s
// = 48.1us = this kernel's time. Structural floor reached.

#define THREADS 256
#define BLOCKS  1216   // 8 blocks/SM x 152 SMs = one full wave

__device__ float        g_partial;   // zero at load; reset by last block each call
__device__ unsigned int g_count;

__device__ __forceinline__ float4 ldcs_256(const float4* p) {
    float4 v;
    asm("ld.global.cs.L2::256B.v4.f32 {%0,%1,%2,%3}, [%4];"
        : "=f"(v.x), "=f"(v.y), "=f"(v.z), "=f"(v.w) : "l"(p));
    return v;
}

__global__ __launch_bounds__(THREADS, 8)
void mlloss_kernel(const float4* __restrict__ dist4,  // [B,16] as B*4 float4
                   const int* __restrict__ doctor,    // [B] int32 {0,1,2}
                   const int* __restrict__ real_l,    // [B] int32 {0,1}
                   float* __restrict__ out,
                   int B, float inv_B)
{
    const int tid    = blockIdx.x * blockDim.x + threadIdx.x;
    const int stride = gridDim.x * blockDim.x;

    float acc = 0.0f;

    for (int row = tid; row < B; row += stride) {
        const int dl = __ldcs(&doctor[row]);
        const int rl = __ldcs(&real_l[row]);

        const size_t base = (size_t)row * 4;
        const float4 a = ldcs_256(&dist4[base + 0]);
        const float4 b = ldcs_256(&dist4[base + 1]);
        const float4 c = ldcs_256(&dist4[base + 2]);
        const float4 d = ldcs_256(&dist4[base + 3]);

        const float h0 = fmaxf(1.0f - a.x, 0.0f);
        const float h1 = fmaxf(1.0f - a.y, 0.0f);
        float hs = h0 + h1
                 + fmaxf(1.0f - a.z, 0.0f) + fmaxf(1.0f - a.w, 0.0f)
                 + fmaxf(1.0f - b.x, 0.0f) + fmaxf(1.0f - b.y, 0.0f)
                 + fmaxf(1.0f - b.z, 0.0f) + fmaxf(1.0f - b.w, 0.0f)
                 + fmaxf(1.0f - c.x, 0.0f) + fmaxf(1.0f - c.y, 0.0f)
                 + fmaxf(1.0f - c.z, 0.0f) + fmaxf(1.0f - c.w, 0.0f)
                 + fmaxf(1.0f - d.x, 0.0f) + fmaxf(1.0f - d.y, 0.0f)
                 + fmaxf(1.0f - d.z, 0.0f) + fmaxf(1.0f - d.w, 0.0f);

        const float loss = (dl == 0) ? (a.x + hs - h0)
                         : (dl == 1) ? (a.y + hs - h1)
                                     : ((rl == 0) ? h1 : h0);
        acc += loss;
    }

    // warp reduce
    #pragma unroll
    for (int off = 16; off > 0; off >>= 1)
        acc += __shfl_xor_sync(0xFFFFFFFFu, acc, off);

    __shared__ float warp_sums[THREADS / 32];
    const int lane = threadIdx.x & 31;
    const int wid  = threadIdx.x >> 5;
    if (lane == 0) warp_sums[wid] = acc;
    __syncthreads();

    if (wid == 0) {
        float v = (lane < THREADS / 32) ? warp_sums[lane] : 0.0f;
        #pragma unroll
        for (int off = 16; off > 0; off >>= 1)
            v += __shfl_xor_sync(0xFFFFFFFFu, v, off);

        if (lane == 0) {
            atomicAdd(&g_partial, v);
            __threadfence();
            const unsigned int ticket = atomicAdd(&g_count, 1u);
            if (ticket == gridDim.x - 1) {
                const float total = atomicAdd(&g_partial, 0.0f); // fenced read
                out[0] = total * inv_B;
                g_partial = 0.0f;
                g_count   = 0u;
                __threadfence();
            }
        }
    }
}

extern "C" void kernel_launch(void* const* d_in, const int* in_sizes, int n_in,
                              void* d_out, int out_size)
{
    const float4* dist4  = (const float4*)d_in[0];
    const int*    doctor = (const int*)d_in[1];
    const int*    real_l = (const int*)d_in[2];
    float*        out    = (float*)d_out;

    const int B = in_sizes[1];
    const float inv_B = 1.0f / (float)B;

    mlloss_kernel<<<BLOCKS, THREADS>>>(dist4, doctor, real_l, out, B, inv_B);
}

// round 15
// speedup vs baseline: 1.1675x; 1.1608x over previous
#include <cuda_runtime.h>
#include <cuda_bf16.h>

// MLLoss: per-sample hinge loss over [B,16] f32 distances -> scalar mean.
// Labels int32.
//
// R15 = best kernel (48.2-48.7us, 6.26-6.34 TB/s = memory-system noise band)
// + L2 prefetch of the NEXT grid-stride iteration's row: zero registers,
// zero scoreboard, one LSU slot (issue is only ~20%), puts the next 64B
// granule in flight ~600cyc early. Last untested lever; everything else
// (LDG.128/256 strided/coalesced/predicated, TMA, work stealing, sector
// skipping, L2 hints) measured and exhausted R2-R14.

#define THREADS 256
#define BLOCKS  1216   // 8 blocks/SM x 152 SMs = one full wave

__device__ float        g_partial;   // zero at load; reset by last block each call
__device__ unsigned int g_count;

__device__ __forceinline__ float4 ldcs_256(const float4* p) {
    float4 v;
    asm("ld.global.cs.L2::256B.v4.f32 {%0,%1,%2,%3}, [%4];"
        : "=f"(v.x), "=f"(v.y), "=f"(v.z), "=f"(v.w) : "l"(p));
    return v;
}

__device__ __forceinline__ void prefetch_l2(const void* p) {
    asm volatile("prefetch.global.L2 [%0];" :: "l"(p));
}

__global__ __launch_bounds__(THREADS, 8)
void mlloss_kernel(const float4* __restrict__ dist4,  // [B,16] as B*4 float4
                   const int* __restrict__ doctor,    // [B] int32 {0,1,2}
                   const int* __restrict__ real_l,    // [B] int32 {0,1}
                   float* __restrict__ out,
                   int B, float inv_B)
{
    const int tid    = blockIdx.x * blockDim.x + threadIdx.x;
    const int stride = gridDim.x * blockDim.x;

    float acc = 0.0f;

    for (int row = tid; row < B; row += stride) {
        const int dl = __ldcs(&doctor[row]);
        const int rl = __ldcs(&real_l[row]);

        const size_t base = (size_t)row * 4;
        const float4 a = ldcs_256(&dist4[base + 0]);
        const float4 b = ldcs_256(&dist4[base + 1]);
        const float4 c = ldcs_256(&dist4[base + 2]);
        const float4 d = ldcs_256(&dist4[base + 3]);

        // put next iteration's granule in flight (no reg/scoreboard cost)
        const int nrow = row + stride;
        if (nrow < B)
            prefetch_l2(&dist4[(size_t)nrow * 4]);

        const float h0 = fmaxf(1.0f - a.x, 0.0f);
        const float h1 = fmaxf(1.0f - a.y, 0.0f);
        float hs = h0 + h1
                 + fmaxf(1.0f - a.z, 0.0f) + fmaxf(1.0f - a.w, 0.0f)
                 + fmaxf(1.0f - b.x, 0.0f) + fmaxf(1.0f - b.y, 0.0f)
                 + fmaxf(1.0f - b.z, 0.0f) + fmaxf(1.0f - b.w, 0.0f)
                 + fmaxf(1.0f - c.x, 0.0f) + fmaxf(1.0f - c.y, 0.0f)
                 + fmaxf(1.0f - c.z, 0.0f) + fmaxf(1.0f - c.w, 0.0f)
                 + fmaxf(1.0f - d.x, 0.0f) + fmaxf(1.0f - d.y, 0.0f)
                 + fmaxf(1.0f - d.z, 0.0f) + fmaxf(1.0f - d.w, 0.0f);

        const float loss = (dl == 0) ? (a.x + hs - h0)
                         : (dl == 1) ? (a.y + hs - h1)
                                     : ((rl == 0) ? h1 : h0);
        acc += loss;
    }

    // warp reduce
    #pragma unroll
    for (int off = 16; off > 0; off >>= 1)
        acc += __shfl_xor_sync(0xFFFFFFFFu, acc, off);

    __shared__ float warp_sums[THREADS / 32];
    const int lane = threadIdx.x & 31;
    const int wid  = threadIdx.x >> 5;
    if (lane == 0) warp_sums[wid] = acc;
    __syncthreads();

    if (wid == 0) {
        float v = (lane < THREADS / 32) ? warp_sums[lane] : 0.0f;
        #pragma unroll
        for (int off = 16; off > 0; off >>= 1)
            v += __shfl_xor_sync(0xFFFFFFFFu, v, off);

        if (lane == 0) {
            atomicAdd(&g_partial, v);
            __threadfence();
            const unsigned int ticket = atomicAdd(&g_count, 1u);
            if (ticket == gridDim.x - 1) {
                const float total = atomicAdd(&g_partial, 0.0f); // fenced read
                out[0] = total * inv_B;
                g_partial = 0.0f;
                g_count   = 0u;
                __threadfence();
            }
        }
    }
}

extern "C" void kernel_launch(void* const* d_in, const int* in_sizes, int n_in,
                              void* d_out, int out_size)
{
    const float4* dist4  = (const float4*)d_in[0];
    const int*    doctor = (const int*)d_in[1];
    const int*    real_l = (const int*)d_in[2];
    float*        out    = (float*)d_out;

    const int B = in_sizes[1];
    const float inv_B = 1.0f / (float)B;

    mlloss_kernel<<<BLOCKS, THREADS>>>(dist4, doctor, real_l, out, B, inv_B);
}